// round 8
// baseline (speedup 1.0000x reference)
#include <cuda_runtime.h>
#include <cuda_bf16.h>
#include <cstdint>

#define N_NODES 50000
#define N_EDGES 800000
#define NV4 32            // float4 per 128-float row
#define D 128
#define AS_STRIDE 132     // 128 + 4 pad floats
#define FUSED_SMEM (128 * AS_STRIDE * 4)   // 67584 bytes

// ---- device scratch (no dynamic allocs allowed) ----
__device__ float4 g_bufA[(size_t)N_NODES * NV4];
__device__ float4 g_bufB[(size_t)N_NODES * NV4];
__device__ float2 g_Wf  [3 * 8192];                // fragment-major tf32 weights
__device__ int    g_out_cnt[N_NODES];
__device__ int    g_in_cnt[N_NODES];
__device__ int    g_cursor[N_NODES];
__device__ int    g_off[N_NODES + 1];
__device__ int    g_csr_src[N_EDGES];
__device__ float  g_out_inv[N_NODES];
__device__ float  g_in_inv[N_NODES];

__device__ __forceinline__ float tf32r(float x) {
    uint32_t u;
    asm("cvt.rna.tf32.f32 %0, %1;" : "=r"(u) : "f"(x));
    return __uint_as_float(u);
}

// ---------------- CSR build ----------------
__global__ void k_init() {
    int i = blockIdx.x * blockDim.x + threadIdx.x;
    if (i < N_NODES) { g_out_cnt[i] = 0; g_in_cnt[i] = 0; g_cursor[i] = 0; }
}

__global__ void k_deg(const int* __restrict__ src,
                      const int* __restrict__ dst) {
    int e = blockIdx.x * blockDim.x + threadIdx.x;
    if (e < N_EDGES) {
        unsigned s = (unsigned)src[e];
        unsigned d = (unsigned)dst[e];
        if (s < N_NODES) atomicAdd(&g_out_cnt[s], 1);
        if (d < N_NODES) atomicAdd(&g_in_cnt[d], 1);
    }
}

__global__ void k_scan() {
    const int T = 1024;
    const int CH = (N_NODES + T - 1) / T;
    __shared__ int part[T];
    int t = threadIdx.x;
    int base = t * CH;
    int s = 0;
    for (int i = 0; i < CH; i++) {
        int idx = base + i;
        if (idx < N_NODES) s += g_in_cnt[idx];
    }
    part[t] = s;
    __syncthreads();
    for (int o = 1; o < T; o <<= 1) {
        int v = (t >= o) ? part[t - o] : 0;
        __syncthreads();
        part[t] += v;
        __syncthreads();
    }
    int run = (t == 0) ? 0 : part[t - 1];
    for (int i = 0; i < CH; i++) {
        int idx = base + i;
        if (idx < N_NODES) { g_off[idx] = run; run += g_in_cnt[idx]; }
    }
    if (t == T - 1) g_off[N_NODES] = run;
    for (int idx = t; idx < N_NODES; idx += T) {
        g_out_inv[idx] = rsqrtf((float)max(g_out_cnt[idx], 1));
        g_in_inv[idx]  = rsqrtf((float)max(g_in_cnt[idx], 1));
    }
}

__global__ void k_fill(const int* __restrict__ src,
                       const int* __restrict__ dst) {
    int e = blockIdx.x * blockDim.x + threadIdx.x;
    if (e < N_EDGES) {
        unsigned s = (unsigned)src[e];
        unsigned d = (unsigned)dst[e];
        if (s < N_NODES && d < N_NODES) {
            int pos = atomicAdd(&g_cursor[d], 1);
            int idx = g_off[d] + pos;
            if ((unsigned)idx < N_EDGES) g_csr_src[idx] = (int)s;
        }
    }
}

// rearrange W into fragment-major tf32: for (kf,nf,lane): tq=lane&3, gid=lane>>2
//   b0 = W[kf*8+tq][nf*8+gid], b1 = W[kf*8+tq+4][nf*8+gid]
__global__ void k_wprep(const float* __restrict__ W0,
                        const float* __restrict__ W1,
                        const float* __restrict__ W2) {
    int i = blockIdx.x * blockDim.x + threadIdx.x;
    if (i >= 3 * 8192) return;
    int l    = i >> 13;
    int r    = i & 8191;
    int kf   = r >> 9;
    int nf   = (r >> 5) & 15;
    int lane = r & 31;
    int tq = lane & 3, gid = lane >> 2;
    const float* W = (l == 0) ? W0 : (l == 1) ? W1 : W2;
    float b0 = W[(kf * 8 + tq) * D + nf * 8 + gid];
    float b1 = W[(kf * 8 + tq + 4) * D + nf * 8 + gid];
    g_Wf[i] = make_float2(tf32r(b0), tf32r(b1));
}

// ---------------- fused layer: gather-aggregate -> smem -> tf32 MMA -> out ----
// phase 1: 8 warps aggregate 128 dst rows (16 rounds) into As (tf32, in_inv applied)
// phase 2: m16n8k8 MMA, warp w owns rows w*16..w*16+15 x all 128 cols
__global__ void __launch_bounds__(256, 2)
k_fused(const float4* __restrict__ xg, int in_sel, int scale_src,
        int out_sel, float* __restrict__ dout, int widx,
        const float* __restrict__ bias, int apply_out) {
    extern __shared__ __align__(16) float As[];   // 128 x AS_STRIDE

    const float4* __restrict__ xin = xg ? xg : (in_sel ? g_bufB : g_bufA);
    float* __restrict__ out = (out_sel == 0) ? (float*)g_bufA
                            : (out_sel == 1) ? (float*)g_bufB : dout;
    const float2* __restrict__ Wf = g_Wf + widx * 8192;

    int lane = threadIdx.x & 31;
    int warp = threadIdx.x >> 5;
    int gid = lane >> 2;     // 0..7
    int tq  = lane & 3;      // 0..3
    int row0 = blockIdx.x * 128;

    // ---- phase 1: aggregate ----
    #pragma unroll 1
    for (int i = 0; i < 16; i++) {
        int r = i * 8 + warp;            // 0..127
        int n = row0 + r;
        float4 acc = make_float4(0.f, 0.f, 0.f, 0.f);
        if (n < N_NODES) {
            int beg = g_off[n], end = g_off[n + 1];
            int k = beg;
            for (; k + 3 < end; k += 4) {
                int s0 = g_csr_src[k + 0];
                int s1 = g_csr_src[k + 1];
                int s2 = g_csr_src[k + 2];
                int s3 = g_csr_src[k + 3];
                float w0 = 1.f, w1 = 1.f, w2 = 1.f, w3 = 1.f;
                if (scale_src) {
                    w0 = g_out_inv[s0]; w1 = g_out_inv[s1];
                    w2 = g_out_inv[s2]; w3 = g_out_inv[s3];
                }
                float4 v0 = xin[s0 * NV4 + lane];
                float4 v1 = xin[s1 * NV4 + lane];
                float4 v2 = xin[s2 * NV4 + lane];
                float4 v3 = xin[s3 * NV4 + lane];
                acc.x = fmaf(v0.x, w0, fmaf(v1.x, w1, fmaf(v2.x, w2, fmaf(v3.x, w3, acc.x))));
                acc.y = fmaf(v0.y, w0, fmaf(v1.y, w1, fmaf(v2.y, w2, fmaf(v3.y, w3, acc.y))));
                acc.z = fmaf(v0.z, w0, fmaf(v1.z, w1, fmaf(v2.z, w2, fmaf(v3.z, w3, acc.z))));
                acc.w = fmaf(v0.w, w0, fmaf(v1.w, w1, fmaf(v2.w, w2, fmaf(v3.w, w3, acc.w))));
            }
            for (; k < end; ++k) {
                int s = g_csr_src[k];
                float w = scale_src ? g_out_inv[s] : 1.f;
                float4 v = xin[s * NV4 + lane];
                acc.x = fmaf(v.x, w, acc.x);
                acc.y = fmaf(v.y, w, acc.y);
                acc.z = fmaf(v.z, w, acc.z);
                acc.w = fmaf(v.w, w, acc.w);
            }
            float sc = g_in_inv[n];
            acc.x = tf32r(acc.x * sc);
            acc.y = tf32r(acc.y * sc);
            acc.z = tf32r(acc.z * sc);
            acc.w = tf32r(acc.w * sc);
        }
        *(float4*)(As + r * AS_STRIDE + lane * 4) = acc;
    }
    __syncthreads();

    // ---- phase 2: MMA ----
    float acc[16][4];
    #pragma unroll
    for (int nf = 0; nf < 16; nf++)
        #pragma unroll
        for (int c = 0; c < 4; c++) acc[nf][c] = 0.f;

    #pragma unroll
    for (int kf = 0; kf < 16; kf++) {
        const float* Ab = As + (warp * 16 + gid) * AS_STRIDE + kf * 8 + tq;
        uint32_t a0 = __float_as_uint(Ab[0]);
        uint32_t a1 = __float_as_uint(Ab[8 * AS_STRIDE]);
        uint32_t a2 = __float_as_uint(Ab[4]);
        uint32_t a3 = __float_as_uint(Ab[8 * AS_STRIDE + 4]);
        const float2* Wk = Wf + (kf << 9) + lane;
        #pragma unroll
        for (int nf = 0; nf < 16; nf++) {
            float2 b = Wk[nf * 32];        // coalesced LDG.64, L1-resident
            asm volatile(
                "mma.sync.aligned.m16n8k8.row.col.f32.tf32.tf32.f32 "
                "{%0,%1,%2,%3}, {%4,%5,%6,%7}, {%8,%9}, {%0,%1,%2,%3};"
                : "+f"(acc[nf][0]), "+f"(acc[nf][1]),
                  "+f"(acc[nf][2]), "+f"(acc[nf][3])
                : "r"(a0), "r"(a1), "r"(a2), "r"(a3),
                  "r"(__float_as_uint(b.x)), "r"(__float_as_uint(b.y)));
        }
    }

    // ---- epilogue: bias + relu (+ out_inv), float2 stores ----
    int rowA = row0 + warp * 16 + gid;
    int rowB = rowA + 8;
    float s0 = 1.f, s1 = 1.f;
    if (apply_out) {
        s0 = g_out_inv[min(rowA, N_NODES - 1)];
        s1 = g_out_inv[min(rowB, N_NODES - 1)];
    }
    #pragma unroll
    for (int nf = 0; nf < 16; nf++) {
        int col = nf * 8 + 2 * tq;
        float2 bv = *(const float2*)(bias + col);
        float v0 = fmaxf(acc[nf][0] + bv.x, 0.f) * s0;
        float v1 = fmaxf(acc[nf][1] + bv.y, 0.f) * s0;
        float v2 = fmaxf(acc[nf][2] + bv.x, 0.f) * s1;
        float v3 = fmaxf(acc[nf][3] + bv.y, 0.f) * s1;
        if (rowA < N_NODES)
            *(float2*)(out + (size_t)rowA * D + col) = make_float2(v0, v1);
        if (rowB < N_NODES)
            *(float2*)(out + (size_t)rowB * D + col) = make_float2(v2, v3);
    }
}

extern "C" void kernel_launch(void* const* d_in, const int* in_sizes, int n_in,
                              void* d_out, int out_size) {
    const float* h   = (const float*)d_in[0];
    const int*   src = (const int*)d_in[1];    // int32: JAX x64 is disabled
    const int*   dst = (const int*)d_in[2];
    const float* W0 = (const float*)d_in[3];
    const float* b0 = (const float*)d_in[4];
    const float* W1 = (const float*)d_in[5];
    const float* b1 = (const float*)d_in[6];
    const float* W2 = (const float*)d_in[7];
    const float* b2 = (const float*)d_in[8];

    static int attr_done = 0;
    if (!attr_done) {
        cudaFuncSetAttribute(k_fused, cudaFuncAttributeMaxDynamicSharedMemorySize,
                             FUSED_SMEM);
        attr_done = 1;
    }

    k_init<<<(N_NODES + 255) / 256, 256>>>();
    k_deg<<<(N_EDGES + 255) / 256, 256>>>(src, dst);
    k_scan<<<1, 1024>>>();
    k_fill<<<(N_EDGES + 255) / 256, 256>>>(src, dst);
    k_wprep<<<(3 * 8192 + 255) / 256, 256>>>(W0, W1, W2);

    const int grid = (N_NODES + 127) / 128;    // 391

    // layer 0: h (src-scaled in gather) -> bufB (out-scaled)
    k_fused<<<grid, 256, FUSED_SMEM>>>((const float4*)h, 0, 1, 1, nullptr, 0, b0, 1);
    // layer 1: bufB -> bufA (out-scaled)
    k_fused<<<grid, 256, FUSED_SMEM>>>(nullptr, 1, 0, 0, nullptr, 1, b1, 1);
    // layer 2: bufA -> d_out (no out-scale)
    k_fused<<<grid, 256, FUSED_SMEM>>>(nullptr, 0, 0, 2, (float*)d_out, 2, b2, 0);
}

// round 10
// speedup vs baseline: 1.2696x; 1.2696x over previous
#include <cuda_runtime.h>
#include <cuda_fp16.h>
#include <cstdint>

#define N_NODES 50000
#define N_EDGES 800000
#define D 128

// ---- device scratch (no dynamic allocs allowed) ----
__device__ __half2 g_hA[(size_t)N_NODES * 64];     // fp16 activations (row = 64 half2)
__device__ __half2 g_hB[(size_t)N_NODES * 64];
__device__ float4  g_m [(size_t)N_NODES * 32];     // tf32-rounded aggregate (f32)
__device__ float2  g_Wf[3 * 8192];                 // fragment-major tf32 weights
__device__ int     g_out_cnt[N_NODES];
__device__ int     g_in_cnt[N_NODES];
__device__ int     g_cursor[N_NODES];
__device__ int     g_off[N_NODES + 1];
__device__ int     g_csr_src[N_EDGES];
__device__ float   g_out_inv[N_NODES];
__device__ float   g_in_inv[N_NODES];

__device__ __forceinline__ float tf32r(float x) {
    uint32_t u;
    asm("cvt.rna.tf32.f32 %0, %1;" : "=r"(u) : "f"(x));
    return __uint_as_float(u);
}

// ---------------- CSR build ----------------
__global__ void k_init() {
    int i = blockIdx.x * blockDim.x + threadIdx.x;
    if (i < N_NODES) { g_out_cnt[i] = 0; g_in_cnt[i] = 0; }
}

__global__ void k_deg(const int* __restrict__ src,
                      const int* __restrict__ dst) {
    int e = blockIdx.x * blockDim.x + threadIdx.x;
    if (e < N_EDGES) {
        unsigned s = (unsigned)src[e];
        unsigned d = (unsigned)dst[e];
        if (s < N_NODES) atomicAdd(&g_out_cnt[s], 1);
        if (d < N_NODES) atomicAdd(&g_in_cnt[d], 1);
    }
}

__global__ void k_scan() {
    const int T = 1024;
    const int CH = (N_NODES + T - 1) / T;
    __shared__ int part[T];
    int t = threadIdx.x;
    int base = t * CH;
    int s = 0;
    for (int i = 0; i < CH; i++) {
        int idx = base + i;
        if (idx < N_NODES) s += g_in_cnt[idx];
    }
    part[t] = s;
    __syncthreads();
    for (int o = 1; o < T; o <<= 1) {
        int v = (t >= o) ? part[t - o] : 0;
        __syncthreads();
        part[t] += v;
        __syncthreads();
    }
    int run = (t == 0) ? 0 : part[t - 1];
    for (int i = 0; i < CH; i++) {
        int idx = base + i;
        if (idx < N_NODES) {
            g_off[idx] = run;
            g_cursor[idx] = run;           // seed cursor = offset
            run += g_in_cnt[idx];
        }
    }
    if (t == T - 1) g_off[N_NODES] = run;
    for (int idx = t; idx < N_NODES; idx += T) {
        g_out_inv[idx] = rsqrtf((float)max(g_out_cnt[idx], 1));
        g_in_inv[idx]  = rsqrtf((float)max(g_in_cnt[idx], 1));
    }
}

__global__ void k_fill(const int* __restrict__ src,
                       const int* __restrict__ dst) {
    int e = blockIdx.x * blockDim.x + threadIdx.x;
    if (e < N_EDGES) {
        unsigned s = (unsigned)src[e];
        unsigned d = (unsigned)dst[e];
        if (s < N_NODES && d < N_NODES) {
            int pos = atomicAdd(&g_cursor[d], 1);
            if ((unsigned)pos < N_EDGES) g_csr_src[pos] = (int)s;
        }
    }
}

// g_hA = fp16(h * out_inv)   (src-side normalization folded in)
__global__ void k_hprep(const float2* __restrict__ h2) {
    int i = blockIdx.x * blockDim.x + threadIdx.x;   // one half2 per thread
    if (i < N_NODES * 64) {
        float sc = g_out_inv[i >> 6];
        float2 v = h2[i];
        g_hA[i] = __floats2half2_rn(v.x * sc, v.y * sc);
    }
}

// fragment-major tf32 weights
__global__ void k_wprep(const float* __restrict__ W0,
                        const float* __restrict__ W1,
                        const float* __restrict__ W2) {
    int i = blockIdx.x * blockDim.x + threadIdx.x;
    if (i >= 3 * 8192) return;
    int l    = i >> 13;
    int r    = i & 8191;
    int kf   = r >> 9;
    int nf   = (r >> 5) & 15;
    int lane = r & 31;
    int tq = lane & 3, gid = lane >> 2;
    const float* W = (l == 0) ? W0 : (l == 1) ? W1 : W2;
    float b0 = W[(kf * 8 + tq) * D + nf * 8 + gid];
    float b1 = W[(kf * 8 + tq + 4) * D + nf * 8 + gid];
    g_Wf[i] = make_float2(tf32r(b0), tf32r(b1));
}

// ---------------- aggregation (fp16 in): m[n] = tf32(in_inv[n] * sum x[src]) ----
// one warp per node; lane owns halves [4*lane, 4*lane+4) of the 128-row
__global__ void __launch_bounds__(256) k_agg(int in_sel) {
    const __half2* __restrict__ xin = in_sel ? g_hB : g_hA;
    int warp = threadIdx.x >> 5;
    int lane = threadIdx.x & 31;
    int n = blockIdx.x * 8 + warp;

    int beg = g_off[n], end = g_off[n + 1];
    float4 acc = make_float4(0.f, 0.f, 0.f, 0.f);
    int k = beg;
    for (; k + 3 < end; k += 4) {
        int s0 = g_csr_src[k + 0];
        int s1 = g_csr_src[k + 1];
        int s2 = g_csr_src[k + 2];
        int s3 = g_csr_src[k + 3];
        uint2 u0 = *(const uint2*)(xin + (size_t)s0 * 64 + lane * 2);
        uint2 u1 = *(const uint2*)(xin + (size_t)s1 * 64 + lane * 2);
        uint2 u2 = *(const uint2*)(xin + (size_t)s2 * 64 + lane * 2);
        uint2 u3 = *(const uint2*)(xin + (size_t)s3 * 64 + lane * 2);
        float2 a0 = __half22float2(*(__half2*)&u0.x), b0 = __half22float2(*(__half2*)&u0.y);
        float2 a1 = __half22float2(*(__half2*)&u1.x), b1 = __half22float2(*(__half2*)&u1.y);
        float2 a2 = __half22float2(*(__half2*)&u2.x), b2 = __half22float2(*(__half2*)&u2.y);
        float2 a3 = __half22float2(*(__half2*)&u3.x), b3 = __half22float2(*(__half2*)&u3.y);
        acc.x += (a0.x + a1.x) + (a2.x + a3.x);
        acc.y += (a0.y + a1.y) + (a2.y + a3.y);
        acc.z += (b0.x + b1.x) + (b2.x + b3.x);
        acc.w += (b0.y + b1.y) + (b2.y + b3.y);
    }
    for (; k < end; ++k) {
        int s = g_csr_src[k];
        uint2 u = *(const uint2*)(xin + (size_t)s * 64 + lane * 2);
        float2 a = __half22float2(*(__half2*)&u.x), b = __half22float2(*(__half2*)&u.y);
        acc.x += a.x; acc.y += a.y; acc.z += b.x; acc.w += b.y;
    }
    float sc = g_in_inv[n];
    float4 r;
    r.x = tf32r(acc.x * sc);
    r.y = tf32r(acc.y * sc);
    r.z = tf32r(acc.z * sc);
    r.w = tf32r(acc.w * sc);
    g_m[n * 32 + lane] = r;
}

// ---------------- GEMM via mma.sync m16n8k8 tf32, smem A-tile + fragment-major W ----
// out_sel: 0 -> g_hA (fp16, out_inv), 1 -> g_hB (fp16, out_inv), 2 -> dout (f32)
__global__ void __launch_bounds__(256, 2)
k_gemm2(int out_sel, float* __restrict__ dout, int widx,
        const float* __restrict__ bias) {
    __shared__ __align__(16) float As[128 * 36];   // 128 rows x 32 k, pad 4

    const float2* __restrict__ Wf = g_Wf + widx * 8192;
    __half2* __restrict__ outh = (out_sel == 0) ? g_hA : g_hB;

    int lane = threadIdx.x & 31;
    int warp = threadIdx.x >> 5;
    int gid = lane >> 2;     // 0..7
    int tq  = lane & 3;      // 0..3
    int row0 = blockIdx.x * 128;

    float acc[16][4];
    #pragma unroll
    for (int nf = 0; nf < 16; nf++)
        #pragma unroll
        for (int c = 0; c < 4; c++) acc[nf][c] = 0.f;

    int lr = threadIdx.x >> 1;                 // 0..127 row within tile
    int lc = (threadIdx.x & 1) * 16;           // 0 or 16 k-offset
    int grow = min(row0 + lr, N_NODES - 1);
    const float* gbase = (const float*)g_m + (size_t)grow * D + lc;

    for (int kt = 0; kt < 128; kt += 32) {
        float4 v0 = *(const float4*)(gbase + kt);
        float4 v1 = *(const float4*)(gbase + kt + 4);
        float4 v2 = *(const float4*)(gbase + kt + 8);
        float4 v3 = *(const float4*)(gbase + kt + 12);
        __syncthreads();
        float* dstp = As + lr * 36 + lc;
        ((float4*)dstp)[0] = v0;
        ((float4*)dstp)[1] = v1;
        ((float4*)dstp)[2] = v2;
        ((float4*)dstp)[3] = v3;
        __syncthreads();

        #pragma unroll
        for (int kf2 = 0; kf2 < 4; kf2++) {
            const float* Ab = As + (warp * 16 + gid) * 36 + kf2 * 8 + tq;
            uint32_t a0 = __float_as_uint(Ab[0]);
            uint32_t a1 = __float_as_uint(Ab[8 * 36]);
            uint32_t a2 = __float_as_uint(Ab[4]);
            uint32_t a3 = __float_as_uint(Ab[8 * 36 + 4]);
            int kf = (kt >> 3) + kf2;
            const float2* Wk = Wf + (kf << 9) + lane;
            #pragma unroll
            for (int nf = 0; nf < 16; nf++) {
                float2 b = Wk[nf * 32];        // coalesced LDG.64, L1-resident
                asm volatile(
                    "mma.sync.aligned.m16n8k8.row.col.f32.tf32.tf32.f32 "
                    "{%0,%1,%2,%3}, {%4,%5,%6,%7}, {%8,%9}, {%0,%1,%2,%3};"
                    : "+f"(acc[nf][0]), "+f"(acc[nf][1]),
                      "+f"(acc[nf][2]), "+f"(acc[nf][3])
                    : "r"(a0), "r"(a1), "r"(a2), "r"(a3),
                      "r"(__float_as_uint(b.x)), "r"(__float_as_uint(b.y)));
            }
        }
    }

    // epilogue: bias + relu, then fp16 (+out_inv) or f32 store
    int rowA = row0 + warp * 16 + gid;
    int rowB = rowA + 8;
    if (out_sel != 2) {
        float s0 = g_out_inv[min(rowA, N_NODES - 1)];
        float s1 = g_out_inv[min(rowB, N_NODES - 1)];
        #pragma unroll
        for (int nf = 0; nf < 16; nf++) {
            int col = nf * 8 + 2 * tq;
            float2 bv = *(const float2*)(bias + col);
            float v0 = fmaxf(acc[nf][0] + bv.x, 0.f) * s0;
            float v1 = fmaxf(acc[nf][1] + bv.y, 0.f) * s0;
            float v2 = fmaxf(acc[nf][2] + bv.x, 0.f) * s1;
            float v3 = fmaxf(acc[nf][3] + bv.y, 0.f) * s1;
            if (rowA < N_NODES)
                outh[(size_t)rowA * 64 + (col >> 1)] = __floats2half2_rn(v0, v1);
            if (rowB < N_NODES)
                outh[(size_t)rowB * 64 + (col >> 1)] = __floats2half2_rn(v2, v3);
        }
    } else {
        #pragma unroll
        for (int nf = 0; nf < 16; nf++) {
            int col = nf * 8 + 2 * tq;
            float2 bv = *(const float2*)(bias + col);
            float v0 = fmaxf(acc[nf][0] + bv.x, 0.f);
            float v1 = fmaxf(acc[nf][1] + bv.y, 0.f);
            float v2 = fmaxf(acc[nf][2] + bv.x, 0.f);
            float v3 = fmaxf(acc[nf][3] + bv.y, 0.f);
            if (rowA < N_NODES)
                *(float2*)(dout + (size_t)rowA * D + col) = make_float2(v0, v1);
            if (rowB < N_NODES)
                *(float2*)(dout + (size_t)rowB * D + col) = make_float2(v2, v3);
        }
    }
}

extern "C" void kernel_launch(void* const* d_in, const int* in_sizes, int n_in,
                              void* d_out, int out_size) {
    const float* h   = (const float*)d_in[0];
    const int*   src = (const int*)d_in[1];    // int32: JAX x64 is disabled
    const int*   dst = (const int*)d_in[2];
    const float* W0 = (const float*)d_in[3];
    const float* b0 = (const float*)d_in[4];
    const float* W1 = (const float*)d_in[5];
    const float* b1 = (const float*)d_in[6];
    const float* W2 = (const float*)d_in[7];
    const float* b2 = (const float*)d_in[8];

    k_init<<<(N_NODES + 255) / 256, 256>>>();
    k_deg<<<(N_EDGES + 255) / 256, 256>>>(src, dst);
    k_scan<<<1, 1024>>>();
    k_fill<<<(N_EDGES + 255) / 256, 256>>>(src, dst);
    k_hprep<<<(N_NODES * 64 + 255) / 256, 256>>>((const float2*)h);
    k_wprep<<<(3 * 8192 + 255) / 256, 256>>>(W0, W1, W2);

    const int agg_grid  = N_NODES / 8;              // 6250, exact
    const int gemm_grid = (N_NODES + 127) / 128;    // 391

    // layer 0: hA -> m -> hB (fp16, out-scaled)
    k_agg  <<<agg_grid, 256>>>(0);
    k_gemm2<<<gemm_grid, 256>>>(1, nullptr, 0, b0);
    // layer 1: hB -> m -> hA (fp16, out-scaled)
    k_agg  <<<agg_grid, 256>>>(1);
    k_gemm2<<<gemm_grid, 256>>>(0, nullptr, 1, b1);
    // layer 2: hA -> m -> d_out (f32, no out-scale)
    k_agg  <<<agg_grid, 256>>>(0);
    k_gemm2<<<gemm_grid, 256>>>(2, (float*)d_out, 2, b2);
}